// round 4
// baseline (speedup 1.0000x reference)
#include <cuda_runtime.h>
#include <cstdint>

// Problem constants
#define Bsz 64
#define Ssz 2048
#define Isz 128
#define Hsz 256
#define G4  1024   // 4*H

// ---------------------------------------------------------------------------
// Device scratch (static allocation — no cudaMalloc allowed)
// ---------------------------------------------------------------------------
__device__ __align__(16) float g_xg[(size_t)Ssz * Bsz * G4];   // [s][b][4H]

// ---------------------------------------------------------------------------
// f32x2 packed helpers
// ---------------------------------------------------------------------------
__device__ __forceinline__ unsigned long long pk2(float lo, float hi) {
    unsigned long long r;
    asm("mov.b64 %0, {%1, %2};" : "=l"(r) : "f"(lo), "f"(hi));
    return r;
}
__device__ __forceinline__ void upk2(unsigned long long v, float& lo, float& hi) {
    asm("mov.b64 {%0, %1}, %2;" : "=f"(lo), "=f"(hi) : "l"(v));
}
__device__ __forceinline__ unsigned long long fma2(unsigned long long a,
                                                   unsigned long long b,
                                                   unsigned long long c) {
    unsigned long long d;
    asm("fma.rn.f32x2 %0, %1, %2, %3;" : "=l"(d) : "l"(a), "l"(b), "l"(c));
    return d;
}
__device__ __forceinline__ uint32_t smem_u32(const void* p) {
    uint32_t a;
    asm("{ .reg .u64 t; cvta.to.shared.u64 t, %1; cvt.u32.u64 %0, t; }"
        : "=r"(a) : "l"(p));
    return a;
}

// ---------------------------------------------------------------------------
// Phase 1: xg[s][b][g*256+h] = b_g[h] + sum_i x[b][s][i] * U_g[i][h]
// Tiled fp32 GEMM (f32x2 packed): M=131072 (r = s*64+b), N=1024, K=128
// ---------------------------------------------------------------------------
#define TM 128
#define TN 64
#define KK 128
#define LDA 132
#define LDB 68
#define SMEM1 ((KK*LDA + KK*LDB) * 4)

__global__ void __launch_bounds__(256) gemm_xg_kernel(
    const float* __restrict__ x,
    const float* __restrict__ Uf, const float* __restrict__ Ui,
    const float* __restrict__ Uo, const float* __restrict__ Uc,
    const float* __restrict__ bf, const float* __restrict__ bi,
    const float* __restrict__ bo, const float* __restrict__ bc)
{
    extern __shared__ float sm[];
    float* As = sm;              // [KK][LDA]  (A transposed: As[k][m])
    float* Bs = sm + KK * LDA;   // [KK][LDB]

    const int tid = threadIdx.x;
    const int r0 = blockIdx.y * TM;
    const int j0 = blockIdx.x * TN;
    const int g  = j0 >> 8;          // gate (tile never crosses gate boundary)
    const int hb = j0 & 255;
    const float* Ug = (g == 0) ? Uf : (g == 1) ? Ui : (g == 2) ? Uo : Uc;
    const float* bg = (g == 0) ? bf : (g == 1) ? bi : (g == 2) ? bo : bc;

    #pragma unroll
    for (int it = 0; it < 16; it++) {
        int idx = it * 256 + tid;          // 4096 float4
        int row = idx & 127;
        int k4  = idx >> 7;                // 0..31
        int r   = r0 + row;
        int bb  = r & 63, ss = r >> 6;
        float4 v = *(const float4*)(x + ((size_t)bb * Ssz + ss) * Isz + k4 * 4);
        As[(k4*4+0)*LDA + row] = v.x;
        As[(k4*4+1)*LDA + row] = v.y;
        As[(k4*4+2)*LDA + row] = v.z;
        As[(k4*4+3)*LDA + row] = v.w;
    }
    #pragma unroll
    for (int it = 0; it < 8; it++) {
        int idx = it * 256 + tid;          // 2048 float4
        int n4 = idx & 15;
        int k  = idx >> 4;
        float4 v = *(const float4*)(Ug + (size_t)k * Hsz + hb + n4 * 4);
        *(float4*)(Bs + k * LDB + n4 * 4) = v;
    }
    __syncthreads();

    const int tn = tid & 15, tm = tid >> 4;
    const int m0 = tm * 8, n0 = tn * 4;

    unsigned long long acc2[8][2];
    #pragma unroll
    for (int i = 0; i < 8; i++) { acc2[i][0] = 0ull; acc2[i][1] = 0ull; }

    #pragma unroll 4
    for (int k = 0; k < KK; k++) {
        float4 b4 = *(float4*)(Bs + k * LDB + n0);
        float4 a0 = *(float4*)(As + k * LDA + m0);
        float4 a1 = *(float4*)(As + k * LDA + m0 + 4);
        unsigned long long b01 = pk2(b4.x, b4.y);
        unsigned long long b23 = pk2(b4.z, b4.w);
        float av[8] = {a0.x,a0.y,a0.z,a0.w,a1.x,a1.y,a1.z,a1.w};
        #pragma unroll
        for (int i = 0; i < 8; i++) {
            unsigned long long ad = pk2(av[i], av[i]);
            acc2[i][0] = fma2(ad, b01, acc2[i][0]);
            acc2[i][1] = fma2(ad, b23, acc2[i][1]);
        }
    }

    float4 bias = *(const float4*)(bg + hb + n0);
    #pragma unroll
    for (int i = 0; i < 8; i++) {
        int r = r0 + m0 + i;
        float c0, c1, c2, c3;
        upk2(acc2[i][0], c0, c1);
        upk2(acc2[i][1], c2, c3);
        float4 o;
        o.x = c0 + bias.x;
        o.y = c1 + bias.y;
        o.z = c2 + bias.z;
        o.w = c3 + bias.w;
        *(float4*)(g_xg + (size_t)r * G4 + j0 + n0) = o;
    }
}

// ---------------------------------------------------------------------------
// Phase 2: sequential LSTM scan with cluster-8 DSMEM h exchange.
// 16 clusters (batch groups of 4) x 8 CTAs. CTA rank c owns hidx [32c,32c+32)
// across all 4 gates; its W slice lives in registers as f32x2 gate-pairs.
// Per step: compute from own h_sm[p], gate math, multicast-store new h into
// all 8 CTAs' h_sm[1-p] via st.shared::cluster, one barrier.cluster.
//
// Thread map (256 threads = 8 warps): warp w, lane l:
//   jsub = l & 3   -> hidx = 32*rank + 4*w + jsub
//   kc   = l >> 2  -> owns interleaved k float4-chunks {kc+8t : t=0..7}
// 8-lane shfl_xor reduction over kc; lane kc==b does gate math for batch b.
// ---------------------------------------------------------------------------
__device__ __forceinline__ float sigf(float v) { return 1.f / (1.f + __expf(-v)); }

#define HSTRIDE 264   // floats per (buf,b) row: pad 256->264 (16B-aligned, bank-staggered)

__global__ void __launch_bounds__(256, 1) __cluster_dims__(8, 1, 1)
lstm_scan_kernel(
    const float* __restrict__ Wf, const float* __restrict__ Wi,
    const float* __restrict__ Wo, const float* __restrict__ Wc,
    float* __restrict__ out, int write_tail)
{
    __shared__ __align__(16) float h_sm[2][4][HSTRIDE];

    const int tid  = threadIdx.x;
    const int wid  = tid >> 5;
    const int lane = tid & 31;
    const int jsub = lane & 3;
    const int kc   = lane >> 2;            // 0..7
    const int grp  = blockIdx.x >> 3;      // 0..15 (cluster id)
    const int csl  = blockIdx.x & 7;       // cluster rank
    const int B0   = grp * 4;
    const int hx   = csl * 32 + wid * 4 + jsub;
    const uint32_t h_base = smem_u32(&h_sm[0][0][0]);

    // Zero initial h (buffer 0) locally.
    for (int i = tid; i < 4 * HSTRIDE; i += 256)
        h_sm[0][i / HSTRIDE][i % HSTRIDE] = 0.f;

    // W slice in registers, packed as gate-pairs: w2[t][e][0]=(Wf,Wi), [1]=(Wo,Wc)
    unsigned long long w2[8][4][2];
    #pragma unroll
    for (int t = 0; t < 8; t++)
        #pragma unroll
        for (int e = 0; e < 4; e++) {
            int k = (kc + 8 * t) * 4 + e;
            size_t off = (size_t)k * Hsz + hx;
            w2[t][e][0] = pk2(__ldg(Wf + off), __ldg(Wi + off));
            w2[t][e][1] = pk2(__ldg(Wo + off), __ldg(Wc + off));
        }

    // Prefetch xg for s=0
    float xv0 = 0.f, xv1 = 0.f, xv2 = 0.f, xv3 = 0.f;
    if (kc < 4) {
        const float* xr = g_xg + ((size_t)0 * Bsz + B0 + kc) * G4 + hx;
        xv0 = __ldg(xr);
        xv1 = __ldg(xr + 256);
        xv2 = __ldg(xr + 512);
        xv3 = __ldg(xr + 768);
    }

    __syncthreads();
    // Initial cluster barrier: all peers' smem initialized before remote stores.
    asm volatile("barrier.cluster.arrive.aligned;" ::: "memory");
    asm volatile("barrier.cluster.wait.aligned;"   ::: "memory");

    float c_st = 0.f, h_fin = 0.f;

    for (int s = 0; s < Ssz; s++) {
        const int p = s & 1;

        // Partial GEMM over this lane's k-chunks (f32x2: gate pairs)
        unsigned long long acc2[4][2];
        #pragma unroll
        for (int b = 0; b < 4; b++) { acc2[b][0] = 0ull; acc2[b][1] = 0ull; }

        #pragma unroll
        for (int t = 0; t < 8; t++) {
            const int j4 = (kc + 8 * t) * 4;
            float4 hv0 = *(const float4*)&h_sm[p][0][j4];
            float4 hv1 = *(const float4*)&h_sm[p][1][j4];
            float4 hv2 = *(const float4*)&h_sm[p][2][j4];
            float4 hv3 = *(const float4*)&h_sm[p][3][j4];
            #pragma unroll
            for (int e = 0; e < 4; e++) {
                float h0 = (e == 0) ? hv0.x : (e == 1) ? hv0.y : (e == 2) ? hv0.z : hv0.w;
                float h1 = (e == 0) ? hv1.x : (e == 1) ? hv1.y : (e == 2) ? hv1.z : hv1.w;
                float h2 = (e == 0) ? hv2.x : (e == 1) ? hv2.y : (e == 2) ? hv2.z : hv2.w;
                float h3 = (e == 0) ? hv3.x : (e == 1) ? hv3.y : (e == 2) ? hv3.z : hv3.w;
                unsigned long long d0 = pk2(h0, h0);
                unsigned long long d1 = pk2(h1, h1);
                unsigned long long d2 = pk2(h2, h2);
                unsigned long long d3 = pk2(h3, h3);
                acc2[0][0] = fma2(d0, w2[t][e][0], acc2[0][0]);
                acc2[0][1] = fma2(d0, w2[t][e][1], acc2[0][1]);
                acc2[1][0] = fma2(d1, w2[t][e][0], acc2[1][0]);
                acc2[1][1] = fma2(d1, w2[t][e][1], acc2[1][1]);
                acc2[2][0] = fma2(d2, w2[t][e][0], acc2[2][0]);
                acc2[2][1] = fma2(d2, w2[t][e][1], acc2[2][1]);
                acc2[3][0] = fma2(d3, w2[t][e][0], acc2[3][0]);
                acc2[3][1] = fma2(d3, w2[t][e][1], acc2[3][1]);
            }
        }

        // Unpack and reduce over the 8 kc-lanes (lane bits 2..4)
        float a[16];
        #pragma unroll
        for (int b = 0; b < 4; b++) {
            upk2(acc2[b][0], a[b*4+0], a[b*4+1]);
            upk2(acc2[b][1], a[b*4+2], a[b*4+3]);
        }
        #pragma unroll
        for (int off = 4; off < 32; off <<= 1)
            #pragma unroll
            for (int i = 0; i < 16; i++)
                a[i] += __shfl_xor_sync(0xffffffffu, a[i], off);

        // Gate math: lane kc==b owns batch b for this hidx
        float h = 0.f;
        if (kc < 4) {
            const int b = kc;
            float f  = sigf(a[b*4+0] + xv0);
            float ii = sigf(a[b*4+1] + xv1);
            float o  = sigf(a[b*4+2] + xv2);
            float ct = sigf(a[b*4+3] + xv3);   // sigmoid candidate (per reference)
            c_st = f * c_st + ii * ct;
            h = o * tanhf(c_st);
            h_fin = h;

            // Multicast h into all 8 CTAs' h_sm[1-p][b][hx]
            uint32_t local = h_base +
                ((uint32_t)(1 - p) * 4 * HSTRIDE + (uint32_t)b * HSTRIDE + (uint32_t)hx) * 4u;
            #pragma unroll
            for (int r = 0; r < 8; r++) {
                uint32_t remote;
                asm("mapa.shared::cluster.u32 %0, %1, %2;" : "=r"(remote) : "r"(local), "r"(r));
                asm volatile("st.shared::cluster.f32 [%0], %1;" :: "r"(remote), "f"(h) : "memory");
            }

            // hidden_seq output
            out[((size_t)(B0 + b) * Ssz + s) * Hsz + hx] = h;
        }

        // Prefetch next step's xg (off critical path, hidden behind barrier)
        float nx0 = 0.f, nx1 = 0.f, nx2 = 0.f, nx3 = 0.f;
        if (kc < 4) {
            int sn = (s + 1 < Ssz) ? (s + 1) : s;
            const float* xr = g_xg + ((size_t)sn * Bsz + B0 + kc) * G4 + hx;
            nx0 = __ldg(xr);
            nx1 = __ldg(xr + 256);
            nx2 = __ldg(xr + 512);
            nx3 = __ldg(xr + 768);
        }

        // Cluster barrier: release our DSMEM stores, acquire peers'.
        asm volatile("barrier.cluster.arrive.aligned;" ::: "memory");
        asm volatile("barrier.cluster.wait.aligned;"   ::: "memory");

        xv0 = nx0; xv1 = nx1; xv2 = nx2; xv3 = nx3;
    }

    if (write_tail && kc < 4) {
        const size_t HS = (size_t)Bsz * Ssz * Hsz;
        out[HS + (size_t)(B0 + kc) * Hsz + hx] = h_fin;                       // h_T
        out[HS + (size_t)Bsz * Hsz + (size_t)(B0 + kc) * Hsz + hx] = c_st;    // c_T
    }
}

// ---------------------------------------------------------------------------
// Launch
// ---------------------------------------------------------------------------
extern "C" void kernel_launch(void* const* d_in, const int* in_sizes, int n_in,
                              void* d_out, int out_size)
{
    const float* x  = (const float*)d_in[0];
    const float* Uf = (const float*)d_in[1];
    const float* Wf = (const float*)d_in[2];
    const float* bf = (const float*)d_in[3];
    const float* Ui = (const float*)d_in[4];
    const float* Wi = (const float*)d_in[5];
    const float* bi = (const float*)d_in[6];
    const float* Uo = (const float*)d_in[7];
    const float* Wo = (const float*)d_in[8];
    const float* bo = (const float*)d_in[9];
    const float* Uc = (const float*)d_in[10];
    const float* Wc = (const float*)d_in[11];
    const float* bc = (const float*)d_in[12];
    float* out = (float*)d_out;

    (void)in_sizes; (void)n_in;

    const long long full = (long long)Bsz * Ssz * Hsz + 2LL * Bsz * Hsz;
    int write_tail = ((long long)out_size >= full) ? 1 : 0;

    cudaFuncSetAttribute(gemm_xg_kernel,
                         cudaFuncAttributeMaxDynamicSharedMemorySize, SMEM1);

    gemm_xg_kernel<<<dim3(16, 1024), 256, SMEM1>>>(x, Uf, Ui, Uo, Uc, bf, bi, bo, bc);
    lstm_scan_kernel<<<128, 256>>>(Wf, Wi, Wo, Wc, out, write_tail);
}

// round 5
// speedup vs baseline: 1.2700x; 1.2700x over previous
#include <cuda_runtime.h>
#include <cstdint>

// Problem constants
#define Bsz 64
#define Ssz 2048
#define Isz 128
#define Hsz 256
#define G4  1024   // 4*H

// ---------------------------------------------------------------------------
// Device scratch (static allocation — no cudaMalloc allowed)
// ---------------------------------------------------------------------------
__device__ __align__(16) float g_xg[(size_t)Ssz * Bsz * G4];   // [s][b][4H]
__device__ __align__(16) float g_hbuf[2][Bsz * Hsz];           // ping-pong h state
__device__ unsigned int g_ctr[16 * 8];                         // per-group counters (padded)

// ---------------------------------------------------------------------------
// f32x2 packed helpers
// ---------------------------------------------------------------------------
__device__ __forceinline__ unsigned long long pk2(float lo, float hi) {
    unsigned long long r;
    asm("mov.b64 %0, {%1, %2};" : "=l"(r) : "f"(lo), "f"(hi));
    return r;
}
__device__ __forceinline__ void upk2(unsigned long long v, float& lo, float& hi) {
    asm("mov.b64 {%0, %1}, %2;" : "=f"(lo), "=f"(hi) : "l"(v));
}
__device__ __forceinline__ unsigned long long fma2(unsigned long long a,
                                                   unsigned long long b,
                                                   unsigned long long c) {
    unsigned long long d;
    asm("fma.rn.f32x2 %0, %1, %2, %3;" : "=l"(d) : "l"(a), "l"(b), "l"(c));
    return d;
}

// ---------------------------------------------------------------------------
// Phase 1: xg[s][b][g*256+h] = b_g[h] + sum_k x[b][s][k] * U_g[k][h]
// k-pair-packed f32x2 GEMM: M=131072 (r = s*64+b), N=1024, K=128.
// A in smem row-major [m][k] (k-pairs free via ulonglong2);
// B in smem transposed [n][k] (k-pairs free via u64 loads).
// ---------------------------------------------------------------------------
#define TM 128
#define TN 64
#define KK 128
#define LDA2 132               // floats/row of As; 528B, 16B-aligned
#define LDB2 134               // floats/row of Bs; 536B, 8B-aligned
#define SMEM1 ((TM*LDA2 + TN*LDB2) * 4)

__global__ void __launch_bounds__(256) gemm_xg_kernel(
    const float* __restrict__ x,
    const float* __restrict__ Uf, const float* __restrict__ Ui,
    const float* __restrict__ Uo, const float* __restrict__ Uc,
    const float* __restrict__ bf, const float* __restrict__ bi,
    const float* __restrict__ bo, const float* __restrict__ bc)
{
    extern __shared__ float sm[];
    float* As = sm;                    // [TM][LDA2]  row-major (m, k)
    float* Bs = sm + TM * LDA2;        // [TN][LDB2]  transposed (n, k)

    const int tid = threadIdx.x;
    const int r0 = blockIdx.y * TM;
    const int j0 = blockIdx.x * TN;
    const int g  = j0 >> 8;            // gate (tile never crosses gate boundary)
    const int hb = j0 & 255;
    const float* Ug = (g == 0) ? Uf : (g == 1) ? Ui : (g == 2) ? Uo : Uc;
    const float* bg = (g == 0) ? bf : (g == 1) ? bi : (g == 2) ? bo : bc;

    // A tile: 128 rows x 128 k, row-major (no transpose needed).
    #pragma unroll
    for (int it = 0; it < 16; it++) {
        int idx = it * 256 + tid;      // 4096 float4
        int k4  = idx & 31;
        int row = idx >> 5;
        int r   = r0 + row;
        int bb  = r & 63, ss = r >> 6;
        float4 v = *(const float4*)(x + ((size_t)bb * Ssz + ss) * Isz + k4 * 4);
        *(float4*)(As + row * LDA2 + k4 * 4) = v;
    }
    // B tile: transpose [k][n] -> Bs[n][k] via 4 scalar STS.
    #pragma unroll
    for (int it = 0; it < 8; it++) {
        int idx = it * 256 + tid;      // 2048 float4
        int n4 = idx & 15;
        int k  = idx >> 4;
        float4 v = *(const float4*)(Ug + (size_t)k * Hsz + hb + n4 * 4);
        Bs[(n4 * 4 + 0) * LDB2 + k] = v.x;
        Bs[(n4 * 4 + 1) * LDB2 + k] = v.y;
        Bs[(n4 * 4 + 2) * LDB2 + k] = v.z;
        Bs[(n4 * 4 + 3) * LDB2 + k] = v.w;
    }
    __syncthreads();

    const int tn = tid & 15, tm = tid >> 4;
    const int m0 = tm * 8, n0 = tn * 4;

    unsigned long long acc2[8][4];
    #pragma unroll
    for (int i = 0; i < 8; i++)
        #pragma unroll
        for (int j = 0; j < 4; j++) acc2[i][j] = 0ull;

    #pragma unroll 4
    for (int kq = 0; kq < KK / 4; kq++) {
        // b k-pairs: free u64 loads (8B aligned)
        unsigned long long bp0[4], bp1[4];
        #pragma unroll
        for (int j = 0; j < 4; j++) {
            const float* bb = Bs + (n0 + j) * LDB2 + kq * 4;
            bp0[j] = *(const unsigned long long*)(bb);
            bp1[j] = *(const unsigned long long*)(bb + 2);
        }
        #pragma unroll
        for (int i = 0; i < 8; i++) {
            ulonglong2 A2 = *(const ulonglong2*)(As + (m0 + i) * LDA2 + kq * 4);
            #pragma unroll
            for (int j = 0; j < 4; j++) {
                acc2[i][j] = fma2(A2.x, bp0[j], acc2[i][j]);
                acc2[i][j] = fma2(A2.y, bp1[j], acc2[i][j]);
            }
        }
    }

    float4 bias = *(const float4*)(bg + hb + n0);
    #pragma unroll
    for (int i = 0; i < 8; i++) {
        int r = r0 + m0 + i;
        float v[4];
        #pragma unroll
        for (int j = 0; j < 4; j++) {
            float lo, hi;
            upk2(acc2[i][j], lo, hi);
            v[j] = lo + hi;
        }
        float4 o;
        o.x = v[0] + bias.x;
        o.y = v[1] + bias.y;
        o.z = v[2] + bias.z;
        o.w = v[3] + bias.w;
        *(float4*)(g_xg + (size_t)r * G4 + j0 + n0) = o;
    }
}

// ---------------------------------------------------------------------------
// Phase 2: sequential LSTM scan. 16 groups x 8 CTAs (grid 128 = 1 wave).
// Group g owns batches [4g,4g+4); CTA slice c owns hidx [32c,32c+32) over all
// 4 gates, with its W slice in REGISTERS packed as k-pairs (f32x2, no MOVs:
// h pairs come free from ulonglong2 smem loads).
//
// Thread map (256 thr = 8 warps): warp w, lane l:
//   jsub = l & 3  -> hidx = 32c + 4w + jsub
//   kc   = l >> 2 -> owns interleaved k float4-chunks {kc+8t}
// 8-lane shfl_xor reduction; lane kc==b does gate math for batch b.
// Exchange: global ping-pong hbuf + per-group monotonic atomic counter.
// ---------------------------------------------------------------------------
__device__ __forceinline__ float sigf(float v) { return 1.f / (1.f + __expf(-v)); }

__global__ void init_ctr_kernel() {
    if (threadIdx.x < 16) g_ctr[threadIdx.x * 8] = 0u;
}

__global__ void __launch_bounds__(256, 1) lstm_scan_kernel(
    const float* __restrict__ Wf, const float* __restrict__ Wi,
    const float* __restrict__ Wo, const float* __restrict__ Wc,
    float* __restrict__ out, int write_tail)
{
    __shared__ __align__(16) float h_sm[2][4][Hsz];

    const int tid  = threadIdx.x;
    const int wid  = tid >> 5;
    const int lane = tid & 31;
    const int jsub = lane & 3;
    const int kc   = lane >> 2;            // 0..7
    const int grp  = blockIdx.x >> 3;      // 0..15
    const int csl  = blockIdx.x & 7;       // 0..7
    const int B0   = grp * 4;
    const int hx   = csl * 32 + wid * 4 + jsub;

    // W slice in registers as k-pairs: w2[t][e2][g] = (W_g[k0][hx], W_g[k0+1][hx]),
    // k0 = (kc+8t)*4 + 2*e2
    unsigned long long w2[8][2][4];
    #pragma unroll
    for (int t = 0; t < 8; t++)
        #pragma unroll
        for (int e2 = 0; e2 < 2; e2++) {
            int k0 = (kc + 8 * t) * 4 + 2 * e2;
            size_t o0 = (size_t)k0 * Hsz + hx;
            size_t o1 = o0 + Hsz;
            w2[t][e2][0] = pk2(__ldg(Wf + o0), __ldg(Wf + o1));
            w2[t][e2][1] = pk2(__ldg(Wi + o0), __ldg(Wi + o1));
            w2[t][e2][2] = pk2(__ldg(Wo + o0), __ldg(Wo + o1));
            w2[t][e2][3] = pk2(__ldg(Wc + o0), __ldg(Wc + o1));
        }

    // h(0) = 0 locally in smem buffer 0 (no cross-CTA init barrier needed).
    for (int i = tid; i < 4 * Hsz; i += 256)
        ((float*)h_sm[0])[i] = 0.f;
    __syncthreads();

    float c_st = 0.f, h_fin = 0.f;
    unsigned int* ctr = &g_ctr[grp * 8];

    for (int s = 0; s < Ssz; s++) {
        const int p = s & 1;

        // Prefetch xg for this step (consumed ~1k cycles later at gate time)
        float xv0 = 0.f, xv1 = 0.f, xv2 = 0.f, xv3 = 0.f;
        if (kc < 4) {
            const float* xr = g_xg + ((size_t)s * Bsz + B0 + kc) * G4 + hx;
            xv0 = __ldg(xr);
            xv1 = __ldg(xr + 256);
            xv2 = __ldg(xr + 512);
            xv3 = __ldg(xr + 768);
        }

        // Partial GEMM, k-pair f32x2: acc2[b][g] holds (even-k sum, odd-k sum)
        unsigned long long acc2[4][4];
        #pragma unroll
        for (int b = 0; b < 4; b++)
            #pragma unroll
            for (int g = 0; g < 4; g++) acc2[b][g] = 0ull;

        #pragma unroll
        for (int t = 0; t < 8; t++) {
            const int j4 = (kc + 8 * t) * 4;
            ulonglong2 H0 = *(const ulonglong2*)&h_sm[p][0][j4];
            ulonglong2 H1 = *(const ulonglong2*)&h_sm[p][1][j4];
            ulonglong2 H2 = *(const ulonglong2*)&h_sm[p][2][j4];
            ulonglong2 H3 = *(const ulonglong2*)&h_sm[p][3][j4];
            #pragma unroll
            for (int g = 0; g < 4; g++) {
                acc2[0][g] = fma2(H0.x, w2[t][0][g], acc2[0][g]);
                acc2[0][g] = fma2(H0.y, w2[t][1][g], acc2[0][g]);
                acc2[1][g] = fma2(H1.x, w2[t][0][g], acc2[1][g]);
                acc2[1][g] = fma2(H1.y, w2[t][1][g], acc2[1][g]);
                acc2[2][g] = fma2(H2.x, w2[t][0][g], acc2[2][g]);
                acc2[2][g] = fma2(H2.y, w2[t][1][g], acc2[2][g]);
                acc2[3][g] = fma2(H3.x, w2[t][0][g], acc2[3][g]);
                acc2[3][g] = fma2(H3.y, w2[t][1][g], acc2[3][g]);
            }
        }

        // Fold (even,odd) and reduce over the 8 kc-lanes (lane bits 2..4)
        float a[16];
        #pragma unroll
        for (int b = 0; b < 4; b++)
            #pragma unroll
            for (int g = 0; g < 4; g++) {
                float lo, hi;
                upk2(acc2[b][g], lo, hi);
                a[b * 4 + g] = lo + hi;
            }
        #pragma unroll
        for (int off = 4; off < 32; off <<= 1)
            #pragma unroll
            for (int i = 0; i < 16; i++)
                a[i] += __shfl_xor_sync(0xffffffffu, a[i], off);

        // Gate math: lane kc==b owns batch b for this hidx
        if (kc < 4) {
            const int b = kc;
            float f  = sigf(a[b * 4 + 0] + xv0);
            float ii = sigf(a[b * 4 + 1] + xv1);
            float o  = sigf(a[b * 4 + 2] + xv2);
            float ct = sigf(a[b * 4 + 3] + xv3);   // sigmoid candidate (per reference)
            c_st = f * c_st + ii * ct;
            float h = o * tanhf(c_st);
            h_fin = h;
            out[((size_t)(B0 + b) * Ssz + s) * Hsz + hx] = h;
            g_hbuf[1 - p][(B0 + b) * Hsz + hx] = h;
            __threadfence();               // publish h before the signal
        }
        __syncthreads();
        if (tid == 0) atomicAdd(ctr, 1u);  // group signal (monotonic epochs)

        if (s + 1 < Ssz) {
            // Wait for all 8 CTAs of this group, then stage h(s+1) into smem.
            if (tid == 0) {
                const unsigned int tgt = 8u * (unsigned)(s + 1);
                unsigned int v;
                do {
                    asm volatile("ld.acquire.gpu.u32 %0, [%1];" : "=r"(v) : "l"(ctr));
                    if (v >= tgt) break;
                    __nanosleep(16);
                } while (1);
            }
            __syncthreads();
            {
                int b  = tid >> 6;
                int k4 = tid & 63;
                float4 v = __ldcg((const float4*)(g_hbuf[1 - p] + (B0 + b) * Hsz + k4 * 4));
                *(float4*)&h_sm[1 - p][b][k4 * 4] = v;
            }
            __syncthreads();
        }
    }

    if (write_tail && kc < 4) {
        const size_t HS = (size_t)Bsz * Ssz * Hsz;
        out[HS + (size_t)(B0 + kc) * Hsz + hx] = h_fin;                       // h_T
        out[HS + (size_t)Bsz * Hsz + (size_t)(B0 + kc) * Hsz + hx] = c_st;    // c_T
    }
}

// ---------------------------------------------------------------------------
// Launch
// ---------------------------------------------------------------------------
extern "C" void kernel_launch(void* const* d_in, const int* in_sizes, int n_in,
                              void* d_out, int out_size)
{
    const float* x  = (const float*)d_in[0];
    const float* Uf = (const float*)d_in[1];
    const float* Wf = (const float*)d_in[2];
    const float* bf = (const float*)d_in[3];
    const float* Ui = (const float*)d_in[4];
    const float* Wi = (const float*)d_in[5];
    const float* bi = (const float*)d_in[6];
    const float* Uo = (const float*)d_in[7];
    const float* Wo = (const float*)d_in[8];
    const float* bo = (const float*)d_in[9];
    const float* Uc = (const float*)d_in[10];
    const float* Wc = (const float*)d_in[11];
    const float* bc = (const float*)d_in[12];
    float* out = (float*)d_out;

    (void)in_sizes; (void)n_in;

    const long long full = (long long)Bsz * Ssz * Hsz + 2LL * Bsz * Hsz;
    int write_tail = ((long long)out_size >= full) ? 1 : 0;

    cudaFuncSetAttribute(gemm_xg_kernel,
                         cudaFuncAttributeMaxDynamicSharedMemorySize, SMEM1);

    init_ctr_kernel<<<1, 32>>>();
    gemm_xg_kernel<<<dim3(16, 1024), 256, SMEM1>>>(x, Uf, Ui, Uo, Uc, bf, bi, bo, bc);
    lstm_scan_kernel<<<128, 256>>>(Wf, Wi, Wo, Wc, out, write_tail);
}